// round 3
// baseline (speedup 1.0000x reference)
#include <cuda_runtime.h>
#include <math.h>
#include <stdint.h>

// Problem constants
#define DIMC 1024
#define EXP  8
#define TT   4096            // tokens = B*N
#define MLPD 4096
#define TOTROW (EXP*TT)      // padded token-expert rows (segment of TT per expert)

// ---------------- scratch (static device allocations; no cudaMalloc) ----------------
__device__ float g_G[(size_t)TOTROW * DIMC];        // gelu(t*tw1+tb1) rows      (128 MB)
__device__ float g_A[(size_t)TOTROW * 2 * DIMC];    // [x | te] concat rows      (256 MB)
__device__ float g_H[(size_t)TOTROW * MLPD];        // hidden after gelu         (512 MB)
__device__ int   g_cnt[EXP];
__device__ int   g_rowsmap[TOTROW];                 // token index per (e,pos)
__device__ float g_gval[TOTROW];                    // gate per (e,pos)
__device__ int   g_toke[2*TT];                      // per-token chosen experts
__device__ float g_tokg[2*TT];                      // per-token gates
__device__ float g_M2[DIMC*EXP];                    // te_w2 @ gate_w[2C:3C]
__device__ float g_b2w[EXP];                        // te_b2 @ gate_w[2C:3C]

__device__ __forceinline__ float gelu_exact(float v) {
    return 0.5f * v * (1.0f + erff(v * 0.70710678118654752f));
}

__device__ __forceinline__ unsigned smem_u32(const void* p) {
    unsigned r;
    asm("{ .reg .u64 t; cvta.to.shared.u64 t, %1; cvt.u32.u64 %0, t; }" : "=r"(r) : "l"(p));
    return r;
}
__device__ __forceinline__ unsigned to_tf32(float f) {
    unsigned r; asm("cvt.rna.tf32.f32 %0, %1;" : "=r"(r) : "f"(f)); return r;
}

// ---------------- prep: fold time-embed second matmul into gating ----------------
__global__ void prep_kernel(const float* __restrict__ te_w2,
                            const float* __restrict__ gate_w,
                            const float* __restrict__ te_b2) {
    int i = blockIdx.x * blockDim.x + threadIdx.x;   // 8192 threads
    if (i < DIMC * EXP) {
        int k = i >> 3, e = i & 7;
        float s = 0.f;
        for (int d = 0; d < DIMC; d++)
            s += te_w2[(size_t)k * DIMC + d] * gate_w[(size_t)(2 * DIMC + d) * EXP + e];
        g_M2[k * EXP + e] = s;
    }
    if (i < EXP) {
        float s = 0.f;
        for (int d = 0; d < DIMC; d++)
            s += te_b2[d] * gate_w[(size_t)(2 * DIMC + d) * EXP + i];
        g_b2w[i] = s;
    }
}

// ---------------- zero output + counters ----------------
__global__ void zero_kernel(float* __restrict__ out) {
    int i = blockIdx.x * blockDim.x + threadIdx.x;
    const int n = TT * DIMC;
    for (; i < n; i += gridDim.x * blockDim.x) out[i] = 0.f;
    if (blockIdx.x == 0 && threadIdx.x < EXP) g_cnt[threadIdx.x] = 0;
}

// ---------------- routing: logits, top-2, softmax, list build ----------------
__global__ void route_kernel(const float* __restrict__ x, const float* __restrict__ p,
                             const float* __restrict__ t,
                             const float* __restrict__ te_w1, const float* __restrict__ te_b1,
                             const float* __restrict__ gw) {
    __shared__ float g[DIMC];
    __shared__ float part[128];
    __shared__ float logits[EXP];
    const int tok = blockIdx.x;
    const int tid = threadIdx.x;
    const float tv = t[tok];
    for (int k = tid; k < DIMC; k += 128) g[k] = gelu_exact(tv * te_w1[k] + te_b1[k]);
    __syncthreads();

    const int e = tid & 7, seg = tid >> 3;
    const float* xr = x + (size_t)tok * DIMC;
    const float* pr = p + (size_t)tok * DIMC;
    float acc = 0.f;
    const int k0 = seg * 64;
    for (int k = k0; k < k0 + 64; k++) {
        acc += xr[k] * gw[(size_t)k * EXP + e];
        acc += pr[k] * gw[(size_t)(DIMC + k) * EXP + e];
        acc += g[k] * g_M2[k * EXP + e];
    }
    part[tid] = acc;
    __syncthreads();
    for (int s = 64; s >= 8; s >>= 1) {
        if (tid < s) part[tid] += part[tid + s];
        __syncthreads();
    }
    if (tid < 8) logits[tid] = part[tid] + g_b2w[tid];
    __syncthreads();

    if (tid == 0) {
        float b = -1e30f; int bi = 0;
        for (int i = 0; i < EXP; i++) { float v = logits[i]; if (v > b) { b = v; bi = i; } }
        float s2 = -1e30f; int si = 0;
        for (int i = 0; i < EXP; i++) { if (i == bi) continue; float v = logits[i]; if (v > s2) { s2 = v; si = i; } }
        float e1 = expf(s2 - b);
        float den = 1.f + e1;
        float gb = 1.f / den, gs = e1 / den;
        int p0 = atomicAdd(&g_cnt[bi], 1);
        g_rowsmap[bi * TT + p0] = tok; g_gval[bi * TT + p0] = gb;
        int p1 = atomicAdd(&g_cnt[si], 1);
        g_rowsmap[si * TT + p1] = tok; g_gval[si * TT + p1] = gs;
        g_toke[2 * tok] = bi;  g_tokg[2 * tok] = gb;
        g_toke[2 * tok + 1] = si; g_tokg[2 * tok + 1] = gs;
    }
}

// ---------------- gather: build A[:,0:C] = x rows, G = gelu(t*tw1+tb1) ----------------
__global__ void gather_kernel(const float* __restrict__ x, const float* __restrict__ t,
                              const float* __restrict__ ex_tw1, const float* __restrict__ ex_tb1) {
    const int e = blockIdx.y, pos = blockIdx.x;
    if (pos >= g_cnt[e]) return;
    const int tok = g_rowsmap[e * TT + pos];
    const float tv = t[tok];
    const int tid = threadIdx.x;
    const float4* xr = (const float4*)(x + (size_t)tok * DIMC);
    float4* ar = (float4*)(g_A + (size_t)(e * TT + pos) * (2 * DIMC));
    for (int k = tid; k < DIMC / 4; k += 256) ar[k] = xr[k];
    const float* w1 = ex_tw1 + (size_t)e * DIMC;
    const float* b1 = ex_tb1 + (size_t)e * DIMC;
    float* Gr = g_G + (size_t)(e * TT + pos) * DIMC;
    for (int k = tid; k < DIMC; k += 256) Gr[k] = gelu_exact(tv * w1[k] + b1[k]);
}

// ---------------- grouped tf32 GEMM ----------------
// MODE 0: te = G[M,1024] @ tw2[1024,1024] + tb2  -> g_A[:,1024:2048]
// MODE 1: H  = gelu(A[M,2048] @ mw1[2048,4096] + mb1)
// MODE 2: Y  = H[M,4096] @ mw2[4096,1024] + mb2; out[token] += gate*Y (atomic)
#define BM 128
#define BN 128
#define BK 16
#define ASTR 20
#define BSTR 136

template <int MODE>
__global__ __launch_bounds__(256) void gemm_tf32_kernel(
    const float* __restrict__ B, const float* __restrict__ bias, float* __restrict__ outp) {
    constexpr int K = (MODE == 0) ? 1024 : (MODE == 1) ? 2048 : 4096;
    constexpr int N = (MODE == 1) ? 4096 : 1024;

    const int e = blockIdx.z;
    const int cnt = g_cnt[e];
    const int m0 = blockIdx.y * BM;
    if (m0 >= cnt) return;
    const int n0 = blockIdx.x * BN;

    const float* Abase = (MODE == 0) ? g_G : (MODE == 1) ? g_A : g_H;
    const float* Ae = Abase + (size_t)e * TT * K;      // lda == K for all modes
    const float* Be = B + (size_t)e * K * N;

    __shared__ float As[2][BM * ASTR];
    __shared__ float Bs[2][BK * BSTR];

    const int tid = threadIdx.x;
    const int lane = tid & 31, warp = tid >> 5;
    const int wm = warp & 3, wn = warp >> 2;           // 4 warps M x 2 warps N
    const int gq = lane >> 2, tg = lane & 3;

    float acc[2][8][4];
#pragma unroll
    for (int a = 0; a < 2; a++)
#pragma unroll
        for (int b = 0; b < 8; b++)
#pragma unroll
            for (int c = 0; c < 4; c++) acc[a][b][c] = 0.f;

    auto load_tiles = [&](int kt, int stage) {
        const int k0 = kt * BK;
#pragma unroll
        for (int c = 0; c < 2; c++) {
            int ch = tid + c * 256;
            int row = ch >> 2, col4 = (ch & 3) << 2;
            unsigned dst = smem_u32(&As[stage][row * ASTR + col4]);
            const float* src = Ae + (size_t)(m0 + row) * K + k0 + col4;
            int bytes = (m0 + row < cnt) ? 16 : 0;
            asm volatile("cp.async.cg.shared.global [%0],[%1],16,%2;\n" ::"r"(dst), "l"(src), "r"(bytes));
        }
#pragma unroll
        for (int c = 0; c < 2; c++) {
            int ch = tid + c * 256;
            int kr = ch >> 5, col4 = (ch & 31) << 2;
            unsigned dst = smem_u32(&Bs[stage][kr * BSTR + col4]);
            const float* src = Be + (size_t)(k0 + kr) * N + n0 + col4;
            asm volatile("cp.async.cg.shared.global [%0],[%1],16,%2;\n" ::"r"(dst), "l"(src), "r"(16));
        }
        asm volatile("cp.async.commit_group;\n");
    };

    const int KT = K / BK;
    load_tiles(0, 0);
    for (int kt = 0; kt < KT; kt++) {
        if (kt + 1 < KT) {
            load_tiles(kt + 1, (kt + 1) & 1);
            asm volatile("cp.async.wait_group 1;\n");
        } else {
            asm volatile("cp.async.wait_group 0;\n");
        }
        __syncthreads();
        const int st = kt & 1;
#pragma unroll
        for (int ks = 0; ks < 2; ks++) {
            unsigned ra[2][4];
#pragma unroll
            for (int mi = 0; mi < 2; mi++) {
                int rb = wm * 32 + mi * 16;
                float a0 = As[st][(rb + gq) * ASTR + ks * 8 + tg];
                float a1 = As[st][(rb + gq + 8) * ASTR + ks * 8 + tg];
                float a2 = As[st][(rb + gq) * ASTR + ks * 8 + tg + 4];
                float a3 = As[st][(rb + gq + 8) * ASTR + ks * 8 + tg + 4];
                ra[mi][0] = to_tf32(a0); ra[mi][1] = to_tf32(a1);
                ra[mi][2] = to_tf32(a2); ra[mi][3] = to_tf32(a3);
            }
#pragma unroll
            for (int nf = 0; nf < 8; nf++) {
                int nb = wn * 64 + nf * 8;
                float b0f = Bs[st][(ks * 8 + tg) * BSTR + nb + gq];
                float b1f = Bs[st][(ks * 8 + tg + 4) * BSTR + nb + gq];
                unsigned rb0 = to_tf32(b0f), rb1 = to_tf32(b1f);
#pragma unroll
                for (int mi = 0; mi < 2; mi++) {
                    asm volatile(
                        "mma.sync.aligned.m16n8k8.row.col.f32.tf32.tf32.f32 "
                        "{%0,%1,%2,%3},{%4,%5,%6,%7},{%8,%9},{%0,%1,%2,%3};"
                        : "+f"(acc[mi][nf][0]), "+f"(acc[mi][nf][1]),
                          "+f"(acc[mi][nf][2]), "+f"(acc[mi][nf][3])
                        : "r"(ra[mi][0]), "r"(ra[mi][1]), "r"(ra[mi][2]), "r"(ra[mi][3]),
                          "r"(rb0), "r"(rb1));
                }
            }
        }
        __syncthreads();
    }

    // epilogue
    const float* be = bias + (size_t)e * N;
#pragma unroll
    for (int mi = 0; mi < 2; mi++) {
#pragma unroll
        for (int i2 = 0; i2 < 2; i2++) {
            const int lm = wm * 32 + mi * 16 + gq + i2 * 8;
            const int m = m0 + lm;
            if (m < cnt) {
                int tok = 0; float gv = 0.f;
                if constexpr (MODE == 2) {
                    tok = g_rowsmap[e * TT + m];
                    gv = g_gval[e * TT + m];
                }
#pragma unroll
                for (int nf = 0; nf < 8; nf++) {
#pragma unroll
                    for (int j = 0; j < 2; j++) {
                        const int col = n0 + wn * 64 + nf * 8 + tg * 2 + j;
                        float v = acc[mi][nf][i2 * 2 + j] + be[col];
                        if constexpr (MODE == 0) {
                            g_A[(size_t)(e * TT + m) * (2 * DIMC) + DIMC + col] = v;
                        } else if constexpr (MODE == 1) {
                            g_H[(size_t)(e * TT + m) * MLPD + col] = gelu_exact(v);
                        } else {
                            atomicAdd(&outp[(size_t)tok * DIMC + col], gv * v);
                        }
                    }
                }
            }
        }
    }
}

// ---------------- moe_loss (deterministic fixed-order reduction) ----------------
__global__ void loss_kernel(float* __restrict__ outp, int out_size) {
    __shared__ float part[256 * EXP];
    const int tid = threadIdx.x;
    float l[EXP];
    for (int e = 0; e < EXP; e++) l[e] = 0.f;
    for (int tk = tid; tk < TT; tk += 256) {
        l[g_toke[2 * tk]] += g_tokg[2 * tk];
        l[g_toke[2 * tk + 1]] += g_tokg[2 * tk + 1];
    }
    for (int e = 0; e < EXP; e++) part[tid * EXP + e] = l[e];
    __syncthreads();
    for (int s = 128; s >= 1; s >>= 1) {
        if (tid < s)
            for (int e = 0; e < EXP; e++) part[tid * EXP + e] += part[(tid + s) * EXP + e];
        __syncthreads();
    }
    if (tid == 0) {
        float m = 0.f;
        for (int e = 0; e < EXP; e++) m += part[e];
        m *= (1.0f / EXP);
        float v = 0.f;
        for (int e = 0; e < EXP; e++) { float d = part[e] - m; v += d * d; }
        v /= (float)(EXP - 1);
        float bal = v / (m * m + 1e-10f);
        if (out_size > TT * DIMC) outp[TT * DIMC] = 2.f * bal;
    }
}

// ---------------- launcher ----------------
extern "C" void kernel_launch(void* const* d_in, const int* in_sizes, int n_in,
                              void* d_out, int out_size) {
    const float* x      = (const float*)d_in[0];
    const float* prompt = (const float*)d_in[1];
    const float* t      = (const float*)d_in[2];
    const float* te_w1  = (const float*)d_in[3];
    const float* te_b1  = (const float*)d_in[4];
    const float* te_w2  = (const float*)d_in[5];
    const float* te_b2  = (const float*)d_in[6];
    const float* gate_w = (const float*)d_in[7];
    const float* ex_tw1 = (const float*)d_in[8];
    const float* ex_tb1 = (const float*)d_in[9];
    const float* ex_tw2 = (const float*)d_in[10];
    const float* ex_tb2 = (const float*)d_in[11];
    const float* ex_mw1 = (const float*)d_in[12];
    const float* ex_mb1 = (const float*)d_in[13];
    const float* ex_mw2 = (const float*)d_in[14];
    const float* ex_mb2 = (const float*)d_in[15];
    float* out = (float*)d_out;
    (void)in_sizes; (void)n_in;

    prep_kernel<<<32, 256>>>(te_w2, gate_w, te_b2);
    zero_kernel<<<1024, 256>>>(out);
    route_kernel<<<TT, 128>>>(x, prompt, t, te_w1, te_b1, gate_w);
    gather_kernel<<<dim3(TT, EXP), 256>>>(x, t, ex_tw1, ex_tb1);

    // MODE0: G @ ex_tw2 -> A[:,C:2C)
    gemm_tf32_kernel<0><<<dim3(1024 / BN, TT / BM, EXP), 256>>>(ex_tw2, ex_tb2, out);
    // MODE1: A @ ex_mw1 -> H (gelu)
    gemm_tf32_kernel<1><<<dim3(4096 / BN, TT / BM, EXP), 256>>>(ex_mw1, ex_mb1, out);
    // MODE2: H @ ex_mw2 -> scatter-combine into out
    gemm_tf32_kernel<2><<<dim3(1024 / BN, TT / BM, EXP), 256>>>(ex_mw2, ex_mb2, out);

    loss_kernel<<<1, 256>>>(out, out_size);
}

// round 5
// speedup vs baseline: 1.0358x; 1.0358x over previous
#include <cuda_runtime.h>
#include <math.h>
#include <stdint.h>

// Problem constants
#define DIMC 1024
#define EXP  8
#define TT   4096            // tokens = B*N
#define MLPD 4096
#define TOTROW (EXP*TT)

// ---------------- scratch (static device allocations; no cudaMalloc) ----------------
__device__ float g_G[(size_t)TOTROW * DIMC];        // gelu(t*tw1+tb1) rows (tf32-rounded)
__device__ float g_A[(size_t)TOTROW * 2 * DIMC];    // [x | te] concat rows (tf32-rounded)
__device__ float g_H[(size_t)TOTROW * MLPD];        // hidden after gelu   (tf32-rounded)
__device__ float g_Y[(size_t)2 * TT * DIMC];        // per-slot expert outputs (gated)
__device__ int   g_cnt[EXP];
__device__ int   g_rowsmap[TOTROW];                 // token index per (e,pos)
__device__ int   g_slot[TOTROW];                    // output slot 2*tok+{0,1} per (e,pos)
__device__ float g_gval[TOTROW];
__device__ int   g_toke[2*TT];
__device__ float g_tokg[2*TT];
__device__ float g_M2[DIMC*EXP];
__device__ float g_b2w[EXP];

// Fast exact-erf gelu: Abramowitz-Stegun 7.1.26, |abs err| <= 1.5e-7
__device__ __forceinline__ float gelu_fast(float v) {
    float u = fabsf(v) * 0.70710678118654752f;
    float t = __fdividef(1.0f, fmaf(0.3275911f, u, 1.0f));
    float p = fmaf(t, 1.061405429f, -1.453152027f);
    p = fmaf(t, p, 1.421413741f);
    p = fmaf(t, p, -0.284496736f);
    p = fmaf(t, p, 0.254829592f);
    p = p * t;
    float er = 1.0f - p * __expf(-u * u);
    er = (v < 0.f) ? -er : er;
    return 0.5f * v * (1.0f + er);
}

__device__ __forceinline__ unsigned smem_u32(const void* p) {
    unsigned r;
    asm("{ .reg .u64 t; cvta.to.shared.u64 t, %1; cvt.u32.u64 %0, t; }" : "=r"(r) : "l"(p));
    return r;
}
__device__ __forceinline__ unsigned to_tf32(float f) {
    unsigned r; asm("cvt.rna.tf32.f32 %0, %1;" : "=r"(r) : "f"(f)); return r;
}
// round value to tf32 grid (store-side rounding so GEMM can skip A-operand cvt)
__device__ __forceinline__ float tf32r(float f) { return __uint_as_float(to_tf32(f)); }

// ---------------- prep: fold time-embed second matmul into gating ----------------
__global__ void prep_kernel(const float* __restrict__ te_w2,
                            const float* __restrict__ gate_w,
                            const float* __restrict__ te_b2) {
    __shared__ float sred[256 * EXP];
    const int tid = threadIdx.x;
    float acc[EXP];
#pragma unroll
    for (int e = 0; e < EXP; e++) acc[e] = 0.f;
    const float* src = (blockIdx.x < DIMC) ? (te_w2 + (size_t)blockIdx.x * DIMC) : te_b2;
    for (int d = tid; d < DIMC; d += 256) {
        float wv = src[d];
        const float* gr = gate_w + (size_t)(2 * DIMC + d) * EXP;
#pragma unroll
        for (int e = 0; e < EXP; e++) acc[e] += wv * gr[e];
    }
#pragma unroll
    for (int e = 0; e < EXP; e++) sred[tid * EXP + e] = acc[e];
    __syncthreads();
    for (int s = 128; s >= 1; s >>= 1) {
        if (tid < s)
#pragma unroll
            for (int e = 0; e < EXP; e++) sred[tid * EXP + e] += sred[(tid + s) * EXP + e];
        __syncthreads();
    }
    if (tid < EXP) {
        if (blockIdx.x < DIMC) g_M2[blockIdx.x * EXP + tid] = sred[tid];
        else g_b2w[tid] = sred[tid];
    }
}

// ---------------- zero counters ----------------
__global__ void zero_kernel() {
    if (threadIdx.x < EXP) g_cnt[threadIdx.x] = 0;
}

// ---------------- routing: logits, top-2, softmax, list build ----------------
__global__ void route_kernel(const float* __restrict__ x, const float* __restrict__ p,
                             const float* __restrict__ t,
                             const float* __restrict__ te_w1, const float* __restrict__ te_b1,
                             const float* __restrict__ gw) {
    __shared__ float g[DIMC];
    __shared__ float part[128];
    __shared__ float logits[EXP];
    const int tok = blockIdx.x;
    const int tid = threadIdx.x;
    const float tv = t[tok];
    for (int k = tid; k < DIMC; k += 128) g[k] = gelu_fast(tv * te_w1[k] + te_b1[k]);
    __syncthreads();

    const int e = tid & 7, seg = tid >> 3;
    const float* xr = x + (size_t)tok * DIMC;
    const float* pr = p + (size_t)tok * DIMC;
    float acc = 0.f;
    const int k0 = seg * 64;
    for (int k = k0; k < k0 + 64; k++) {
        acc += xr[k] * gw[(size_t)k * EXP + e];
        acc += pr[k] * gw[(size_t)(DIMC + k) * EXP + e];
        acc += g[k] * g_M2[k * EXP + e];
    }
    part[tid] = acc;
    __syncthreads();
    for (int s = 64; s >= 8; s >>= 1) {
        if (tid < s) part[tid] += part[tid + s];
        __syncthreads();
    }
    if (tid < 8) logits[tid] = part[tid] + g_b2w[tid];
    __syncthreads();

    if (tid == 0) {
        float b = -1e30f; int bi = 0;
        for (int i = 0; i < EXP; i++) { float v = logits[i]; if (v > b) { b = v; bi = i; } }
        float s2 = -1e30f; int si = 0;
        for (int i = 0; i < EXP; i++) { if (i == bi) continue; float v = logits[i]; if (v > s2) { s2 = v; si = i; } }
        float e1 = expf(s2 - b);
        float den = 1.f + e1;
        float gb = 1.f / den, gs = e1 / den;
        int p0 = atomicAdd(&g_cnt[bi], 1);
        g_rowsmap[bi * TT + p0] = tok; g_gval[bi * TT + p0] = gb; g_slot[bi * TT + p0] = 2 * tok;
        int p1 = atomicAdd(&g_cnt[si], 1);
        g_rowsmap[si * TT + p1] = tok; g_gval[si * TT + p1] = gs; g_slot[si * TT + p1] = 2 * tok + 1;
        g_toke[2 * tok] = bi;  g_tokg[2 * tok] = gb;
        g_toke[2 * tok + 1] = si; g_tokg[2 * tok + 1] = gs;
    }
}

// ---------------- gather: A[:,0:C] = tf32(x rows), G = tf32(gelu(t*tw1+tb1)) ----------
__global__ void gather_kernel(const float* __restrict__ x, const float* __restrict__ t,
                              const float* __restrict__ ex_tw1, const float* __restrict__ ex_tb1) {
    const int e = blockIdx.y, pos = blockIdx.x;
    if (pos >= g_cnt[e]) return;
    const int tok = g_rowsmap[e * TT + pos];
    const float tv = t[tok];
    const int tid = threadIdx.x;
    const float4* xr = (const float4*)(x + (size_t)tok * DIMC);
    float4* ar = (float4*)(g_A + (size_t)(e * TT + pos) * (2 * DIMC));
    for (int k = tid; k < DIMC / 4; k += 256) {
        float4 v = xr[k];
        v.x = tf32r(v.x); v.y = tf32r(v.y); v.z = tf32r(v.z); v.w = tf32r(v.w);
        ar[k] = v;
    }
    const float* w1 = ex_tw1 + (size_t)e * DIMC;
    const float* b1 = ex_tb1 + (size_t)e * DIMC;
    float* Gr = g_G + (size_t)(e * TT + pos) * DIMC;
    for (int k = tid; k < DIMC; k += 256) Gr[k] = tf32r(gelu_fast(tv * w1[k] + b1[k]));
}

// ---------------- grouped tf32 GEMM (legacy mma.sync path) ----------------
// MODE 0: te = G[M,1024] @ tw2[1024,1024] + tb2  -> g_A[:,1024:2048] (tf32-rounded)
// MODE 1: H  = gelu(A[M,2048] @ mw1[2048,4096] + mb1)  (tf32-rounded)
// MODE 2: Y  = H[M,4096] @ mw2[4096,1024] + mb2; g_Y[slot] = gate*Y (no atomics)
#define BM 128
#define BN 128
#define BK 16
#define ASTR 20
#define BSTR 136

template <int MODE>
__global__ __launch_bounds__(256) void gemm_tf32_kernel(
    const float* __restrict__ B, const float* __restrict__ bias, float* __restrict__ outp) {
    constexpr int K = (MODE == 0) ? 1024 : (MODE == 1) ? 2048 : 4096;
    constexpr int N = (MODE == 1) ? 4096 : 1024;

    const int e = blockIdx.z;
    const int cnt = g_cnt[e];
    const int m0 = blockIdx.y * BM;
    if (m0 >= cnt) return;
    const int n0 = blockIdx.x * BN;

    const float* Abase = (MODE == 0) ? g_G : (MODE == 1) ? g_A : g_H;
    const float* Ae = Abase + (size_t)e * TT * K;      // lda == K for all modes
    const float* Be = B + (size_t)e * K * N;

    __shared__ float As[2][BM * ASTR];
    __shared__ float Bs[2][BK * BSTR];

    const int tid = threadIdx.x;
    const int lane = tid & 31, warp = tid >> 5;
    const int wm = warp & 3, wn = warp >> 2;           // 4 warps M x 2 warps N
    const int gq = lane >> 2, tg = lane & 3;

    float acc[2][8][4];
#pragma unroll
    for (int a = 0; a < 2; a++)
#pragma unroll
        for (int b = 0; b < 8; b++)
#pragma unroll
            for (int c = 0; c < 4; c++) acc[a][b][c] = 0.f;

    auto load_tiles = [&](int kt, int stage) {
        const int k0 = kt * BK;
#pragma unroll
        for (int c = 0; c < 2; c++) {
            int ch = tid + c * 256;
            int row = ch >> 2, col4 = (ch & 3) << 2;
            unsigned dst = smem_u32(&As[stage][row * ASTR + col4]);
            const float* src = Ae + (size_t)(m0 + row) * K + k0 + col4;
            int bytes = (m0 + row < cnt) ? 16 : 0;
            asm volatile("cp.async.cg.shared.global [%0],[%1],16,%2;\n" ::"r"(dst), "l"(src), "r"(bytes));
        }
#pragma unroll
        for (int c = 0; c < 2; c++) {
            int ch = tid + c * 256;
            int kr = ch >> 5, col4 = (ch & 31) << 2;
            unsigned dst = smem_u32(&Bs[stage][kr * BSTR + col4]);
            const float* src = Be + (size_t)(k0 + kr) * N + n0 + col4;
            asm volatile("cp.async.cg.shared.global [%0],[%1],16,%2;\n" ::"r"(dst), "l"(src), "r"(16));
        }
        asm volatile("cp.async.commit_group;\n");
    };

    const int KT = K / BK;
    load_tiles(0, 0);
    for (int kt = 0; kt < KT; kt++) {
        if (kt + 1 < KT) {
            load_tiles(kt + 1, (kt + 1) & 1);
            asm volatile("cp.async.wait_group 1;\n");
        } else {
            asm volatile("cp.async.wait_group 0;\n");
        }
        __syncthreads();
        const int st = kt & 1;
#pragma unroll
        for (int ks = 0; ks < 2; ks++) {
            unsigned ra[2][4];
#pragma unroll
            for (int mi = 0; mi < 2; mi++) {
                int rb = wm * 32 + mi * 16;
                // A scratch is pre-rounded to tf32 -> pass raw bits (no cvt)
                ra[mi][0] = __float_as_uint(As[st][(rb + gq) * ASTR + ks * 8 + tg]);
                ra[mi][1] = __float_as_uint(As[st][(rb + gq + 8) * ASTR + ks * 8 + tg]);
                ra[mi][2] = __float_as_uint(As[st][(rb + gq) * ASTR + ks * 8 + tg + 4]);
                ra[mi][3] = __float_as_uint(As[st][(rb + gq + 8) * ASTR + ks * 8 + tg + 4]);
            }
#pragma unroll
            for (int nf = 0; nf < 8; nf++) {
                int nb = wn * 64 + nf * 8;
                float b0f = Bs[st][(ks * 8 + tg) * BSTR + nb + gq];
                float b1f = Bs[st][(ks * 8 + tg + 4) * BSTR + nb + gq];
                unsigned rb0 = to_tf32(b0f), rb1 = to_tf32(b1f);
#pragma unroll
                for (int mi = 0; mi < 2; mi++) {
                    asm volatile(
                        "mma.sync.aligned.m16n8k8.row.col.f32.tf32.tf32.f32 "
                        "{%0,%1,%2,%3},{%4,%5,%6,%7},{%8,%9},{%0,%1,%2,%3};"
                        : "+f"(acc[mi][nf][0]), "+f"(acc[mi][nf][1]),
                          "+f"(acc[mi][nf][2]), "+f"(acc[mi][nf][3])
                        : "r"(ra[mi][0]), "r"(ra[mi][1]), "r"(ra[mi][2]), "r"(ra[mi][3]),
                          "r"(rb0), "r"(rb1));
                }
            }
        }
        __syncthreads();
    }

    // epilogue
    const float* be = bias + (size_t)e * N;
#pragma unroll
    for (int mi = 0; mi < 2; mi++) {
#pragma unroll
        for (int i2 = 0; i2 < 2; i2++) {
            const int lm = wm * 32 + mi * 16 + gq + i2 * 8;
            const int m = m0 + lm;
            if (m < cnt) {
                if constexpr (MODE == 2) {
                    const int slot = g_slot[e * TT + m];
                    const float gv = g_gval[e * TT + m];
                    float* yrow = g_Y + (size_t)slot * DIMC;
#pragma unroll
                    for (int nf = 0; nf < 8; nf++) {
                        const int col = n0 + wn * 64 + nf * 8 + tg * 2;
                        float2 v;
                        v.x = gv * (acc[mi][nf][i2 * 2 + 0] + be[col]);
                        v.y = gv * (acc[mi][nf][i2 * 2 + 1] + be[col + 1]);
                        *(float2*)(yrow + col) = v;
                    }
                } else {
#pragma unroll
                    for (int nf = 0; nf < 8; nf++) {
#pragma unroll
                        for (int j = 0; j < 2; j++) {
                            const int col = n0 + wn * 64 + nf * 8 + tg * 2 + j;
                            float v = acc[mi][nf][i2 * 2 + j] + be[col];
                            if constexpr (MODE == 0) {
                                g_A[(size_t)(e * TT + m) * (2 * DIMC) + DIMC + col] = tf32r(v);
                            } else {
                                g_H[(size_t)(e * TT + m) * MLPD + col] = tf32r(gelu_fast(v));
                            }
                        }
                    }
                }
            }
        }
    }
}

// ---------------- combine: out[tok] = Y[2*tok] + Y[2*tok+1] ----------------
__global__ void combine_kernel(float* __restrict__ outp) {
    const int idx = blockIdx.x * blockDim.x + threadIdx.x;   // over TT*256 float4s
    if (idx >= TT * (DIMC / 4)) return;
    const int tk = idx >> 8, c4 = idx & 255;
    const float4 a = ((const float4*)(g_Y + (size_t)(2 * tk) * DIMC))[c4];
    const float4 b = ((const float4*)(g_Y + (size_t)(2 * tk + 1) * DIMC))[c4];
    float4 o;
    o.x = a.x + b.x; o.y = a.y + b.y; o.z = a.z + b.z; o.w = a.w + b.w;
    ((float4*)(outp + (size_t)tk * DIMC))[c4] = o;
}

// ---------------- moe_loss (deterministic fixed-order reduction) ----------------
__global__ void loss_kernel(float* __restrict__ outp, int out_size) {
    __shared__ float part[256 * EXP];
    const int tid = threadIdx.x;
    float l[EXP];
    for (int e = 0; e < EXP; e++) l[e] = 0.f;
    for (int tk = tid; tk < TT; tk += 256) {
        l[g_toke[2 * tk]] += g_tokg[2 * tk];
        l[g_toke[2 * tk + 1]] += g_tokg[2 * tk + 1];
    }
    for (int e = 0; e < EXP; e++) part[tid * EXP + e] = l[e];
    __syncthreads();
    for (int s = 128; s >= 1; s >>= 1) {
        if (tid < s)
            for (int e = 0; e < EXP; e++) part[tid * EXP + e] += part[(tid + s) * EXP + e];
        __syncthreads();
    }
    if (tid == 0) {
        float m = 0.f;
        for (int e = 0; e < EXP; e++) m += part[e];
        m *= (1.0f / EXP);
        float v = 0.f;
        for (int e = 0; e < EXP; e++) { float d = part[e] - m; v += d * d; }
        v /= (float)(EXP - 1);
        float bal = v / (m * m + 1e-10f);
        if (out_size > TT * DIMC) outp[TT * DIMC] = 2.f * bal;
    }
}

// ---------------- launcher ----------------
// Launch order is arranged so ncu (-s 5 -c 1) captures gemm1 (the 137 GF GEMM).
extern "C" void kernel_launch(void* const* d_in, const int* in_sizes, int n_in,
                              void* d_out, int out_size) {
    const float* x      = (const float*)d_in[0];
    const float* prompt = (const float*)d_in[1];
    const float* t      = (const float*)d_in[2];
    const float* te_w1  = (const float*)d_in[3];
    const float* te_b1  = (const float*)d_in[4];
    const float* te_w2  = (const float*)d_in[5];
    const float* te_b2  = (const float*)d_in[6];
    const float* gate_w = (const float*)d_in[7];
    const float* ex_tw1 = (const float*)d_in[8];
    const float* ex_tb1 = (const float*)d_in[9];
    const float* ex_tw2 = (const float*)d_in[10];
    const float* ex_tb2 = (const float*)d_in[11];
    const float* ex_mw1 = (const float*)d_in[12];
    const float* ex_mb1 = (const float*)d_in[13];
    const float* ex_mw2 = (const float*)d_in[14];
    const float* ex_mb2 = (const float*)d_in[15];
    float* out = (float*)d_out;
    (void)in_sizes; (void)n_in;

    prep_kernel<<<DIMC + 1, 256>>>(te_w2, gate_w, te_b2);          // launch 1
    zero_kernel<<<1, 32>>>();                                       // launch 2
    route_kernel<<<TT, 128>>>(x, prompt, t, te_w1, te_b1, gate_w);  // launch 3
    gather_kernel<<<dim3(TT, EXP), 256>>>(x, t, ex_tw1, ex_tb1);    // launch 4

    // MODE0: G @ ex_tw2 -> A[:,C:2C)                               // launch 5
    gemm_tf32_kernel<0><<<dim3(1024 / BN, TT / BM, EXP), 256>>>(ex_tw2, ex_tb2, out);
    // MODE1: A @ ex_mw1 -> H (gelu)                                // launch 6 (ncu capture)
    gemm_tf32_kernel<1><<<dim3(4096 / BN, TT / BM, EXP), 256>>>(ex_mw1, ex_mb1, out);
    // MODE2: H @ ex_mw2 -> g_Y (gated, slot-indexed)               // launch 7
    gemm_tf32_kernel<2><<<dim3(1024 / BN, TT / BM, EXP), 256>>>(ex_mw2, ex_mb2, out);

    combine_kernel<<<(TT * (DIMC / 4) + 255) / 256, 256>>>(out);    // launch 8
    loss_kernel<<<1, 256>>>(out, out_size);                         // launch 9
}

// round 8
// speedup vs baseline: 1.1508x; 1.1110x over previous
#include <cuda_runtime.h>
#include <math.h>
#include <stdint.h>

// Problem constants
#define DIMC 1024
#define EXP  8
#define TT   4096            // tokens = B*N
#define MLPD 4096
#define TOTROW (EXP*TT)

// ---------------- scratch (static device allocations; no cudaMalloc) ----------------
__device__ float g_G[(size_t)TOTROW * DIMC];        // gelu(t*tw1+tb1) rows (tf32-rounded)
__device__ float g_A[(size_t)TOTROW * 2 * DIMC];    // [x | te] concat rows (tf32-rounded)
__device__ float g_H[(size_t)TOTROW * MLPD];        // hidden after gelu   (tf32-rounded)
__device__ float g_Y[(size_t)2 * TT * DIMC];        // per-slot expert outputs (gated)
__device__ int   g_cnt[EXP];
__device__ int   g_rowsmap[TOTROW];
__device__ int   g_slot[TOTROW];
__device__ float g_gval[TOTROW];
__device__ int   g_toke[2*TT];
__device__ float g_tokg[2*TT];
__device__ float g_M2[DIMC*EXP];
__device__ float g_b2w[EXP];

// Fast exact-erf gelu: Abramowitz-Stegun 7.1.26, |abs err| <= 1.5e-7
__device__ __forceinline__ float gelu_fast(float v) {
    float u = fabsf(v) * 0.70710678118654752f;
    float t = __fdividef(1.0f, fmaf(0.3275911f, u, 1.0f));
    float p = fmaf(t, 1.061405429f, -1.453152027f);
    p = fmaf(t, p, 1.421413741f);
    p = fmaf(t, p, -0.284496736f);
    p = fmaf(t, p, 0.254829592f);
    p = p * t;
    float er = 1.0f - p * __expf(-u * u);
    er = (v < 0.f) ? -er : er;
    return 0.5f * v * (1.0f + er);
}

__device__ __forceinline__ unsigned smem_u32(const void* p) {
    unsigned r;
    asm("{ .reg .u64 t; cvta.to.shared.u64 t, %1; cvt.u32.u64 %0, t; }" : "=r"(r) : "l"(p));
    return r;
}
__device__ __forceinline__ unsigned to_tf32(float f) {
    unsigned r; asm("cvt.rna.tf32.f32 %0, %1;" : "=r"(r) : "f"(f)); return r;
}
__device__ __forceinline__ float tf32r(float f) { return __uint_as_float(to_tf32(f)); }

// ---------------- prep: fold time-embed second matmul into gating + zero counters ----
__global__ void prep_kernel(const float* __restrict__ te_w2,
                            const float* __restrict__ gate_w,
                            const float* __restrict__ te_b2) {
    __shared__ float sred[256 * EXP];
    const int tid = threadIdx.x;
    if (blockIdx.x == 0 && tid < EXP) g_cnt[tid] = 0;
    float acc[EXP];
#pragma unroll
    for (int e = 0; e < EXP; e++) acc[e] = 0.f;
    const float* src = (blockIdx.x < DIMC) ? (te_w2 + (size_t)blockIdx.x * DIMC) : te_b2;
    for (int d = tid; d < DIMC; d += 256) {
        float wv = src[d];
        const float* gr = gate_w + (size_t)(2 * DIMC + d) * EXP;
#pragma unroll
        for (int e = 0; e < EXP; e++) acc[e] += wv * gr[e];
    }
#pragma unroll
    for (int e = 0; e < EXP; e++) sred[tid * EXP + e] = acc[e];
    __syncthreads();
    for (int s = 128; s >= 1; s >>= 1) {
        if (tid < s)
#pragma unroll
            for (int e = 0; e < EXP; e++) sred[tid * EXP + e] += sred[(tid + s) * EXP + e];
        __syncthreads();
    }
    if (tid < EXP) {
        if (blockIdx.x < DIMC) g_M2[blockIdx.x * EXP + tid] = sred[tid];
        else g_b2w[tid] = sred[tid];
    }
}

// ---------------- routing + gather fused: logits, top-2, softmax, scatter rows -------
__global__ void route_kernel(const float* __restrict__ x, const float* __restrict__ p,
                             const float* __restrict__ t,
                             const float* __restrict__ te_w1, const float* __restrict__ te_b1,
                             const float* __restrict__ gw,
                             const float* __restrict__ ex_tw1, const float* __restrict__ ex_tb1) {
    __shared__ float g[DIMC];
    __shared__ float part[128];
    __shared__ float logits[EXP];
    __shared__ int   s_e[2], s_p[2];
    const int tok = blockIdx.x;
    const int tid = threadIdx.x;
    const float tv = t[tok];
    for (int k = tid; k < DIMC; k += 128) g[k] = gelu_fast(tv * te_w1[k] + te_b1[k]);
    __syncthreads();

    const int e = tid & 7, seg = tid >> 3;
    const float* xr = x + (size_t)tok * DIMC;
    const float* pr = p + (size_t)tok * DIMC;
    float acc = 0.f;
    const int k0 = seg * 64;
    for (int k = k0; k < k0 + 64; k++) {
        acc += xr[k] * gw[(size_t)k * EXP + e];
        acc += pr[k] * gw[(size_t)(DIMC + k) * EXP + e];
        acc += g[k] * g_M2[k * EXP + e];
    }
    part[tid] = acc;
    __syncthreads();
    for (int s = 64; s >= 8; s >>= 1) {
        if (tid < s) part[tid] += part[tid + s];
        __syncthreads();
    }
    if (tid < 8) logits[tid] = part[tid] + g_b2w[tid];
    __syncthreads();

    if (tid == 0) {
        float b = -1e30f; int bi = 0;
        for (int i = 0; i < EXP; i++) { float v = logits[i]; if (v > b) { b = v; bi = i; } }
        float s2 = -1e30f; int si = 0;
        for (int i = 0; i < EXP; i++) { if (i == bi) continue; float v = logits[i]; if (v > s2) { s2 = v; si = i; } }
        float e1 = expf(s2 - b);
        float den = 1.f + e1;
        float gb = 1.f / den, gs = e1 / den;
        int p0 = atomicAdd(&g_cnt[bi], 1);
        g_rowsmap[bi * TT + p0] = tok; g_gval[bi * TT + p0] = gb; g_slot[bi * TT + p0] = 2 * tok;
        int p1 = atomicAdd(&g_cnt[si], 1);
        g_rowsmap[si * TT + p1] = tok; g_gval[si * TT + p1] = gs; g_slot[si * TT + p1] = 2 * tok + 1;
        g_toke[2 * tok] = bi;  g_tokg[2 * tok] = gb;
        g_toke[2 * tok + 1] = si; g_tokg[2 * tok + 1] = gs;
        s_e[0] = bi; s_p[0] = p0; s_e[1] = si; s_p[1] = p1;
    }
    __syncthreads();

    // fused gather: scatter tf32(x) into both expert A rows, compute G rows
    const int e0 = s_e[0], q0 = s_p[0], e1s = s_e[1], q1 = s_p[1];
    const float4* xr4 = (const float4*)xr;
    float4* a0 = (float4*)(g_A + (size_t)(e0 * TT + q0) * (2 * DIMC));
    float4* a1 = (float4*)(g_A + (size_t)(e1s * TT + q1) * (2 * DIMC));
    for (int k = tid; k < DIMC / 4; k += 128) {
        float4 v = xr4[k];
        v.x = tf32r(v.x); v.y = tf32r(v.y); v.z = tf32r(v.z); v.w = tf32r(v.w);
        a0[k] = v; a1[k] = v;
    }
#pragma unroll
    for (int j = 0; j < 2; j++) {
        const int ee = s_e[j], pp = s_p[j];
        const float* w1 = ex_tw1 + (size_t)ee * DIMC;
        const float* b1 = ex_tb1 + (size_t)ee * DIMC;
        float* Gr = g_G + (size_t)(ee * TT + pp) * DIMC;
        for (int k = tid; k < DIMC; k += 128) Gr[k] = tf32r(gelu_fast(tv * w1[k] + b1[k]));
    }
}

// ---------------- grouped tf32 GEMM: 3-stage cp.async ring, BK=32, 1 barrier/step ----
// MODE 0: te = G[M,1024] @ tw2 + tb2  -> g_A[:,1024:2048] (tf32-rounded)
// MODE 1: H  = gelu(A[M,2048] @ mw1 + mb1)  (tf32-rounded)
// MODE 2: Y  = H[M,4096] @ mw2 + mb2; g_Y[slot] = gate*Y (no atomics)
#define BM 128
#define BN 128
#define BK 32
#define STGS 3
#define ASTR 36
#define BSTR 136
#define A_STAGE (BM * ASTR)
#define B_STAGE (BK * BSTR)
#define GEMM_SMEM (STGS * (A_STAGE + B_STAGE) * 4)

template <int MODE>
__global__ __launch_bounds__(256, 2) void gemm_tf32_kernel(
    const float* __restrict__ B, const float* __restrict__ bias, float* __restrict__ outp) {
    constexpr int K = (MODE == 0) ? 1024 : (MODE == 1) ? 2048 : 4096;
    constexpr int N = (MODE == 1) ? 4096 : 1024;

    const int e = blockIdx.z;
    const int cnt = g_cnt[e];
    const int m0 = blockIdx.y * BM;
    if (m0 >= cnt) return;
    const int n0 = blockIdx.x * BN;

    const float* Abase = (MODE == 0) ? g_G : (MODE == 1) ? g_A : g_H;
    const float* Ae = Abase + ((size_t)e * TT + m0) * K;   // lda == K
    const float* Be = B + (size_t)e * K * N + n0;

    extern __shared__ float sm[];
    float* Asm = sm;
    float* Bsm = sm + STGS * A_STAGE;

    const int tid = threadIdx.x;
    const int lane = tid & 31, warp = tid >> 5;
    const int wm = warp & 3, wn = warp >> 2;           // 4 warps M x 2 warps N
    const int gq = lane >> 2, tg = lane & 3;

    float acc[2][8][4];
#pragma unroll
    for (int a = 0; a < 2; a++)
#pragma unroll
        for (int b = 0; b < 8; b++)
#pragma unroll
            for (int c = 0; c < 4; c++) acc[a][b][c] = 0.f;

    auto load_tile = [&](int kt, int st) {
        const int k0 = kt * BK;
        float* as = Asm + st * A_STAGE;
        float* bs = Bsm + st * B_STAGE;
#pragma unroll
        for (int i = 0; i < 4; i++) {                    // A: 128 rows x 32 floats
            int ch = tid + i * 256;
            int row = ch >> 3, c4 = (ch & 7) << 2;
            unsigned dst = smem_u32(as + row * ASTR + c4);
            const float* src = Ae + (size_t)row * K + k0 + c4;
            asm volatile("cp.async.cg.shared.global [%0],[%1],16;\n" ::"r"(dst), "l"(src));
        }
#pragma unroll
        for (int i = 0; i < 4; i++) {                    // B: 32 rows x 128 floats
            int ch = tid + i * 256;
            int kr = ch >> 5, c4 = (ch & 31) << 2;
            unsigned dst = smem_u32(bs + kr * BSTR + c4);
            const float* src = Be + (size_t)(k0 + kr) * N + c4;
            asm volatile("cp.async.cg.shared.global [%0],[%1],16;\n" ::"r"(dst), "l"(src));
        }
        asm volatile("cp.async.commit_group;\n");
    };

    constexpr int KT = K / BK;
    load_tile(0, 0);
    load_tile(1, 1);

    int st = 0, ld = 2;                                  // stage counters mod 3
    for (int kt = 0; kt < KT; kt++) {
        if (kt + 2 < KT) { asm volatile("cp.async.wait_group 1;\n"); }
        else             { asm volatile("cp.async.wait_group 0;\n"); }
        __syncthreads();
        // issue next loads AFTER the barrier: stage `ld` was last read at iter kt-1,
        // and every warp passed this barrier only after finishing that read.
        if (kt + 2 < KT) {
            load_tile(kt + 2, ld);
            if (++ld == STGS) ld = 0;
        }
        const float* as = Asm + st * A_STAGE;
        const float* bs = Bsm + st * B_STAGE;
#pragma unroll
        for (int ks = 0; ks < 4; ks++) {
            unsigned ra[2][4];
#pragma unroll
            for (int mi = 0; mi < 2; mi++) {
                int rb = wm * 32 + mi * 16;
                // A scratch pre-rounded to tf32 -> raw bits, no cvt
                ra[mi][0] = __float_as_uint(as[(rb + gq) * ASTR + ks * 8 + tg]);
                ra[mi][1] = __float_as_uint(as[(rb + gq + 8) * ASTR + ks * 8 + tg]);
                ra[mi][2] = __float_as_uint(as[(rb + gq) * ASTR + ks * 8 + tg + 4]);
                ra[mi][3] = __float_as_uint(as[(rb + gq + 8) * ASTR + ks * 8 + tg + 4]);
            }
#pragma unroll
            for (int nf = 0; nf < 8; nf++) {
                int nb = wn * 64 + nf * 8;
                unsigned rb0 = to_tf32(bs[(ks * 8 + tg) * BSTR + nb + gq]);
                unsigned rb1 = to_tf32(bs[(ks * 8 + tg + 4) * BSTR + nb + gq]);
#pragma unroll
                for (int mi = 0; mi < 2; mi++) {
                    asm volatile(
                        "mma.sync.aligned.m16n8k8.row.col.f32.tf32.tf32.f32 "
                        "{%0,%1,%2,%3},{%4,%5,%6,%7},{%8,%9},{%0,%1,%2,%3};"
                        : "+f"(acc[mi][nf][0]), "+f"(acc[mi][nf][1]),
                          "+f"(acc[mi][nf][2]), "+f"(acc[mi][nf][3])
                        : "r"(ra[mi][0]), "r"(ra[mi][1]), "r"(ra[mi][2]), "r"(ra[mi][3]),
                          "r"(rb0), "r"(rb1));
                }
            }
        }
        if (++st == STGS) st = 0;
    }

    // epilogue
    const float* be = bias + (size_t)e * N;
#pragma unroll
    for (int mi = 0; mi < 2; mi++) {
#pragma unroll
        for (int i2 = 0; i2 < 2; i2++) {
            const int lm = wm * 32 + mi * 16 + gq + i2 * 8;
            const int m = m0 + lm;
            if (m < cnt) {
                if constexpr (MODE == 2) {
                    const int slot = g_slot[e * TT + m];
                    const float gv = g_gval[e * TT + m];
                    float* yrow = g_Y + (size_t)slot * DIMC;
#pragma unroll
                    for (int nf = 0; nf < 8; nf++) {
                        const int col = n0 + wn * 64 + nf * 8 + tg * 2;
                        float2 v;
                        v.x = gv * (acc[mi][nf][i2 * 2 + 0] + be[col]);
                        v.y = gv * (acc[mi][nf][i2 * 2 + 1] + be[col + 1]);
                        *(float2*)(yrow + col) = v;
                    }
                } else {
#pragma unroll
                    for (int nf = 0; nf < 8; nf++) {
#pragma unroll
                        for (int j = 0; j < 2; j++) {
                            const int col = n0 + wn * 64 + nf * 8 + tg * 2 + j;
                            float v = acc[mi][nf][i2 * 2 + j] + be[col];
                            if constexpr (MODE == 0) {
                                g_A[(size_t)(e * TT + m) * (2 * DIMC) + DIMC + col] = tf32r(v);
                            } else {
                                g_H[(size_t)(e * TT + m) * MLPD + col] = tf32r(gelu_fast(v));
                            }
                        }
                    }
                }
            }
        }
    }
}

// ---------------- combine: out[tok] = Y[2*tok] + Y[2*tok+1] ----------------
__global__ void combine_kernel(float* __restrict__ outp) {
    const int idx = blockIdx.x * blockDim.x + threadIdx.x;
    if (idx >= TT * (DIMC / 4)) return;
    const int tk = idx >> 8, c4 = idx & 255;
    const float4 a = ((const float4*)(g_Y + (size_t)(2 * tk) * DIMC))[c4];
    const float4 b = ((const float4*)(g_Y + (size_t)(2 * tk + 1) * DIMC))[c4];
    float4 o;
    o.x = a.x + b.x; o.y = a.y + b.y; o.z = a.z + b.z; o.w = a.w + b.w;
    ((float4*)(outp + (size_t)tk * DIMC))[c4] = o;
}

// ---------------- moe_loss (deterministic fixed-order reduction) ----------------
__global__ void loss_kernel(float* __restrict__ outp, int out_size) {
    __shared__ float part[256 * EXP];
    const int tid = threadIdx.x;
    float l[EXP];
    for (int e = 0; e < EXP; e++) l[e] = 0.f;
    for (int tk = tid; tk < TT; tk += 256) {
        l[g_toke[2 * tk]] += g_tokg[2 * tk];
        l[g_toke[2 * tk + 1]] += g_tokg[2 * tk + 1];
    }
    for (int e = 0; e < EXP; e++) part[tid * EXP + e] = l[e];
    __syncthreads();
    for (int s = 128; s >= 1; s >>= 1) {
        if (tid < s)
            for (int e = 0; e < EXP; e++) part[tid * EXP + e] += part[(tid + s) * EXP + e];
        __syncthreads();
    }
    if (tid == 0) {
        float m = 0.f;
        for (int e = 0; e < EXP; e++) m += part[e];
        m *= (1.0f / EXP);
        float v = 0.f;
        for (int e = 0; e < EXP; e++) { float d = part[e] - m; v += d * d; }
        v /= (float)(EXP - 1);
        float bal = v / (m * m + 1e-10f);
        if (out_size > TT * DIMC) outp[TT * DIMC] = 2.f * bal;
    }
}

// ---------------- launcher ----------------
// Launch order: prep(1), route(2), gemm0(3), gemm1(4) <- ncu capture slot, gemm2(5), ...
extern "C" void kernel_launch(void* const* d_in, const int* in_sizes, int n_in,
                              void* d_out, int out_size) {
    const float* x      = (const float*)d_in[0];
    const float* prompt = (const float*)d_in[1];
    const float* t      = (const float*)d_in[2];
    const float* te_w1  = (const float*)d_in[3];
    const float* te_b1  = (const float*)d_in[4];
    const float* te_w2  = (const float*)d_in[5];
    const float* te_b2  = (const float*)d_in[6];
    const float* gate_w = (const float*)d_in[7];
    const float* ex_tw1 = (const float*)d_in[8];
    const float* ex_tb1 = (const float*)d_in[9];
    const float* ex_tw2 = (const float*)d_in[10];
    const float* ex_tb2 = (const float*)d_in[11];
    const float* ex_mw1 = (const float*)d_in[12];
    const float* ex_mb1 = (const float*)d_in[13];
    const float* ex_mw2 = (const float*)d_in[14];
    const float* ex_mb2 = (const float*)d_in[15];
    float* out = (float*)d_out;
    (void)in_sizes; (void)n_in;

    static int smem_set = 0;
    if (!smem_set) {
        cudaFuncSetAttribute(gemm_tf32_kernel<0>, cudaFuncAttributeMaxDynamicSharedMemorySize, GEMM_SMEM);
        cudaFuncSetAttribute(gemm_tf32_kernel<1>, cudaFuncAttributeMaxDynamicSharedMemorySize, GEMM_SMEM);
        cudaFuncSetAttribute(gemm_tf32_kernel<2>, cudaFuncAttributeMaxDynamicSharedMemorySize, GEMM_SMEM);
        smem_set = 1;
    }

    prep_kernel<<<DIMC + 1, 256>>>(te_w2, gate_w, te_b2);
    route_kernel<<<TT, 128>>>(x, prompt, t, te_w1, te_b1, gate_w, ex_tw1, ex_tb1);

    gemm_tf32_kernel<0><<<dim3(1024 / BN, TT / BM, EXP), 256, GEMM_SMEM>>>(ex_tw2, ex_tb2, out);
    gemm_tf32_kernel<1><<<dim3(4096 / BN, TT / BM, EXP), 256, GEMM_SMEM>>>(ex_mw1, ex_mb1, out);
    gemm_tf32_kernel<2><<<dim3(1024 / BN, TT / BM, EXP), 256, GEMM_SMEM>>>(ex_mw2, ex_mb2, out);

    combine_kernel<<<(TT * (DIMC / 4) + 255) / 256, 256>>>(out);
    loss_kernel<<<1, 256>>>(out, out_size);
}

// round 9
// speedup vs baseline: 1.2696x; 1.1033x over previous
#include <cuda_runtime.h>
#include <math.h>
#include <stdint.h>

// Problem constants
#define DIMC 1024
#define EXP  8
#define TT   4096            // tokens = B*N
#define MLPD 4096
#define TOTROW (EXP*TT)

// ---------------- scratch (static device allocations; no cudaMalloc) ----------------
__device__ float g_G[(size_t)TOTROW * DIMC];        // gelu(t*tw1+tb1) rows (tf32-rounded)
__device__ float g_A[(size_t)TOTROW * 2 * DIMC];    // [x | te] concat rows (tf32-rounded)
__device__ float g_H[(size_t)TOTROW * MLPD];        // hidden after gelu   (tf32-rounded)
__device__ float g_Y[(size_t)2 * TT * DIMC];        // per-slot expert outputs (gated)
__device__ int   g_cnt[EXP];
__device__ int   g_rowsmap[TOTROW];
__device__ int   g_slot[TOTROW];
__device__ float g_gval[TOTROW];
__device__ int   g_toke[2*TT];
__device__ float g_tokg[2*TT];
__device__ float g_M2[DIMC*EXP];
__device__ float g_b2w[EXP];

// Fast exact-erf gelu: Abramowitz-Stegun 7.1.26, |abs err| <= 1.5e-7
__device__ __forceinline__ float gelu_fast(float v) {
    float u = fabsf(v) * 0.70710678118654752f;
    float t = __fdividef(1.0f, fmaf(0.3275911f, u, 1.0f));
    float p = fmaf(t, 1.061405429f, -1.453152027f);
    p = fmaf(t, p, 1.421413741f);
    p = fmaf(t, p, -0.284496736f);
    p = fmaf(t, p, 0.254829592f);
    p = p * t;
    float er = 1.0f - p * __expf(-u * u);
    er = (v < 0.f) ? -er : er;
    return 0.5f * v * (1.0f + er);
}

__device__ __forceinline__ unsigned smem_u32(const void* p) {
    unsigned r;
    asm("{ .reg .u64 t; cvta.to.shared.u64 t, %1; cvt.u32.u64 %0, t; }" : "=r"(r) : "l"(p));
    return r;
}
__device__ __forceinline__ unsigned to_tf32(float f) {
    unsigned r; asm("cvt.rna.tf32.f32 %0, %1;" : "=r"(r) : "f"(f)); return r;
}
__device__ __forceinline__ float tf32r(float f) { return __uint_as_float(to_tf32(f)); }

// ---------------- prep: fold time-embed second matmul into gating + zero counters ----
__global__ void prep_kernel(const float* __restrict__ te_w2,
                            const float* __restrict__ gate_w,
                            const float* __restrict__ te_b2) {
    __shared__ float sred[256 * EXP];
    const int tid = threadIdx.x;
    if (blockIdx.x == 0 && tid < EXP) g_cnt[tid] = 0;
    float acc[EXP];
#pragma unroll
    for (int e = 0; e < EXP; e++) acc[e] = 0.f;
    const float* src = (blockIdx.x < DIMC) ? (te_w2 + (size_t)blockIdx.x * DIMC) : te_b2;
    for (int d = tid; d < DIMC; d += 256) {
        float wv = src[d];
        const float* gr = gate_w + (size_t)(2 * DIMC + d) * EXP;
#pragma unroll
        for (int e = 0; e < EXP; e++) acc[e] += wv * gr[e];
    }
#pragma unroll
    for (int e = 0; e < EXP; e++) sred[tid * EXP + e] = acc[e];
    __syncthreads();
    for (int s = 128; s >= 1; s >>= 1) {
        if (tid < s)
#pragma unroll
            for (int e = 0; e < EXP; e++) sred[tid * EXP + e] += sred[(tid + s) * EXP + e];
        __syncthreads();
    }
    if (tid < EXP) {
        if (blockIdx.x < DIMC) g_M2[blockIdx.x * EXP + tid] = sred[tid];
        else g_b2w[tid] = sred[tid];
    }
}

// ---------------- routing + gather fused: logits, top-2, softmax, scatter rows -------
__global__ void route_kernel(const float* __restrict__ x, const float* __restrict__ p,
                             const float* __restrict__ t,
                             const float* __restrict__ te_w1, const float* __restrict__ te_b1,
                             const float* __restrict__ gw,
                             const float* __restrict__ ex_tw1, const float* __restrict__ ex_tb1) {
    __shared__ float g[DIMC];
    __shared__ float part[128];
    __shared__ float logits[EXP];
    __shared__ int   s_e[2], s_p[2];
    const int tok = blockIdx.x;
    const int tid = threadIdx.x;
    const float tv = t[tok];
    for (int k = tid; k < DIMC; k += 128) g[k] = gelu_fast(tv * te_w1[k] + te_b1[k]);
    __syncthreads();

    const int e = tid & 7, seg = tid >> 3;
    const float* xr = x + (size_t)tok * DIMC;
    const float* pr = p + (size_t)tok * DIMC;
    float acc = 0.f;
    const int k0 = seg * 64;
    for (int k = k0; k < k0 + 64; k++) {
        acc += xr[k] * gw[(size_t)k * EXP + e];
        acc += pr[k] * gw[(size_t)(DIMC + k) * EXP + e];
        acc += g[k] * g_M2[k * EXP + e];
    }
    part[tid] = acc;
    __syncthreads();
    for (int s = 64; s >= 8; s >>= 1) {
        if (tid < s) part[tid] += part[tid + s];
        __syncthreads();
    }
    if (tid < 8) logits[tid] = part[tid] + g_b2w[tid];
    __syncthreads();

    if (tid == 0) {
        float b = -1e30f; int bi = 0;
        for (int i = 0; i < EXP; i++) { float v = logits[i]; if (v > b) { b = v; bi = i; } }
        float s2 = -1e30f; int si = 0;
        for (int i = 0; i < EXP; i++) { if (i == bi) continue; float v = logits[i]; if (v > s2) { s2 = v; si = i; } }
        float e1 = expf(s2 - b);
        float den = 1.f + e1;
        float gb = 1.f / den, gs = e1 / den;
        int p0 = atomicAdd(&g_cnt[bi], 1);
        g_rowsmap[bi * TT + p0] = tok; g_gval[bi * TT + p0] = gb; g_slot[bi * TT + p0] = 2 * tok;
        int p1 = atomicAdd(&g_cnt[si], 1);
        g_rowsmap[si * TT + p1] = tok; g_gval[si * TT + p1] = gs; g_slot[si * TT + p1] = 2 * tok + 1;
        g_toke[2 * tok] = bi;  g_tokg[2 * tok] = gb;
        g_toke[2 * tok + 1] = si; g_tokg[2 * tok + 1] = gs;
        s_e[0] = bi; s_p[0] = p0; s_e[1] = si; s_p[1] = p1;
    }
    __syncthreads();

    // fused gather: scatter tf32(x) into both expert A rows, compute G rows
    const int e0 = s_e[0], q0 = s_p[0], e1s = s_e[1], q1 = s_p[1];
    const float4* xr4 = (const float4*)xr;
    float4* a0 = (float4*)(g_A + (size_t)(e0 * TT + q0) * (2 * DIMC));
    float4* a1 = (float4*)(g_A + (size_t)(e1s * TT + q1) * (2 * DIMC));
    for (int k = tid; k < DIMC / 4; k += 128) {
        float4 v = xr4[k];
        v.x = tf32r(v.x); v.y = tf32r(v.y); v.z = tf32r(v.z); v.w = tf32r(v.w);
        a0[k] = v; a1[k] = v;
    }
#pragma unroll
    for (int j = 0; j < 2; j++) {
        const int ee = s_e[j], pp = s_p[j];
        const float* w1 = ex_tw1 + (size_t)ee * DIMC;
        const float* b1 = ex_tb1 + (size_t)ee * DIMC;
        float* Gr = g_G + (size_t)(ee * TT + pp) * DIMC;
        for (int k = tid; k < DIMC; k += 128) Gr[k] = tf32r(gelu_fast(tv * w1[k] + b1[k]));
    }
}

// ---------------- grouped tf32 GEMM: CTA 128x128, 4 warps of 64x64, 3-stage ring -----
// MODE 0: te = G[M,1024] @ tw2 + tb2  -> g_A[:,1024:2048] (tf32-rounded)
// MODE 1: H  = gelu(A[M,2048] @ mw1 + mb1)  (tf32-rounded)
// MODE 2: Y  = H[M,4096] @ mw2 + mb2; g_Y[slot] = gate*Y (no atomics)
#define BM 128
#define BN 128
#define BK 32
#define STGS 3
#define ASTR 36
#define BSTR 136
#define A_STAGE (BM * ASTR)
#define B_STAGE (BK * BSTR)
#define GEMM_SMEM (STGS * (A_STAGE + B_STAGE) * 4)

template <int MODE>
__global__ __launch_bounds__(128, 2) void gemm_tf32_kernel(
    const float* __restrict__ B, const float* __restrict__ bias, float* __restrict__ outp) {
    constexpr int K = (MODE == 0) ? 1024 : (MODE == 1) ? 2048 : 4096;
    constexpr int N = (MODE == 1) ? 4096 : 1024;

    const int e = blockIdx.z;
    const int cnt = g_cnt[e];
    const int m0 = blockIdx.y * BM;
    if (m0 >= cnt) return;
    const int n0 = blockIdx.x * BN;

    const float* Abase = (MODE == 0) ? g_G : (MODE == 1) ? g_A : g_H;
    const float* Ae = Abase + ((size_t)e * TT + m0) * K;   // lda == K
    const float* Be = B + (size_t)e * K * N + n0;

    extern __shared__ float sm[];
    float* Asm = sm;
    float* Bsm = sm + STGS * A_STAGE;

    const int tid = threadIdx.x;
    const int lane = tid & 31, warp = tid >> 5;
    const int wm = warp & 1, wn = warp >> 1;           // 2x2 warps, each 64M x 64N
    const int gq = lane >> 2, tg = lane & 3;

    float acc[4][8][4];
#pragma unroll
    for (int a = 0; a < 4; a++)
#pragma unroll
        for (int b = 0; b < 8; b++)
#pragma unroll
            for (int c = 0; c < 4; c++) acc[a][b][c] = 0.f;

    auto load_tile = [&](int kt, int st) {
        const int k0 = kt * BK;
        float* as = Asm + st * A_STAGE;
        float* bs = Bsm + st * B_STAGE;
#pragma unroll
        for (int i = 0; i < 8; i++) {                    // A: 128 rows x 32 floats
            int ch = tid + i * 128;
            int row = ch >> 3, c4 = (ch & 7) << 2;
            unsigned dst = smem_u32(as + row * ASTR + c4);
            const float* src = Ae + (size_t)row * K + k0 + c4;
            asm volatile("cp.async.cg.shared.global [%0],[%1],16;\n" ::"r"(dst), "l"(src));
        }
#pragma unroll
        for (int i = 0; i < 8; i++) {                    // B: 32 rows x 128 floats
            int ch = tid + i * 128;
            int kr = ch >> 5, c4 = (ch & 31) << 2;
            unsigned dst = smem_u32(bs + kr * BSTR + c4);
            const float* src = Be + (size_t)(k0 + kr) * N + c4;
            asm volatile("cp.async.cg.shared.global [%0],[%1],16;\n" ::"r"(dst), "l"(src));
        }
        asm volatile("cp.async.commit_group;\n");
    };

    constexpr int KT = K / BK;
    load_tile(0, 0);
    load_tile(1, 1);

    int st = 0, ld = 2;                                  // stage counters mod 3
    for (int kt = 0; kt < KT; kt++) {
        if (kt + 2 < KT) { asm volatile("cp.async.wait_group 1;\n"); }
        else             { asm volatile("cp.async.wait_group 0;\n"); }
        __syncthreads();
        // issue next loads AFTER the barrier: stage `ld` was last read at iter kt-1,
        // and every warp passed this barrier only after finishing that read.
        if (kt + 2 < KT) {
            load_tile(kt + 2, ld);
            if (++ld == STGS) ld = 0;
        }
        const float* as = Asm + st * A_STAGE;
        const float* bs = Bsm + st * B_STAGE;
#pragma unroll
        for (int ks = 0; ks < 4; ks++) {
            unsigned ra[4][4];
#pragma unroll
            for (int mi = 0; mi < 4; mi++) {
                int rb = wm * 64 + mi * 16;
                // A scratch pre-rounded to tf32 -> raw bits, no cvt
                ra[mi][0] = __float_as_uint(as[(rb + gq) * ASTR + ks * 8 + tg]);
                ra[mi][1] = __float_as_uint(as[(rb + gq + 8) * ASTR + ks * 8 + tg]);
                ra[mi][2] = __float_as_uint(as[(rb + gq) * ASTR + ks * 8 + tg + 4]);
                ra[mi][3] = __float_as_uint(as[(rb + gq + 8) * ASTR + ks * 8 + tg + 4]);
            }
#pragma unroll
            for (int nf = 0; nf < 8; nf++) {
                int nb = wn * 64 + nf * 8;
                unsigned rb0 = to_tf32(bs[(ks * 8 + tg) * BSTR + nb + gq]);
                unsigned rb1 = to_tf32(bs[(ks * 8 + tg + 4) * BSTR + nb + gq]);
#pragma unroll
                for (int mi = 0; mi < 4; mi++) {
                    asm volatile(
                        "mma.sync.aligned.m16n8k8.row.col.f32.tf32.tf32.f32 "
                        "{%0,%1,%2,%3},{%4,%5,%6,%7},{%8,%9},{%0,%1,%2,%3};"
                        : "+f"(acc[mi][nf][0]), "+f"(acc[mi][nf][1]),
                          "+f"(acc[mi][nf][2]), "+f"(acc[mi][nf][3])
                        : "r"(ra[mi][0]), "r"(ra[mi][1]), "r"(ra[mi][2]), "r"(ra[mi][3]),
                          "r"(rb0), "r"(rb1));
                }
            }
        }
        if (++st == STGS) st = 0;
    }

    // epilogue
    const float* be = bias + (size_t)e * N;
#pragma unroll
    for (int mi = 0; mi < 4; mi++) {
#pragma unroll
        for (int i2 = 0; i2 < 2; i2++) {
            const int lm = wm * 64 + mi * 16 + gq + i2 * 8;
            const int m = m0 + lm;
            if (m < cnt) {
                if constexpr (MODE == 2) {
                    const int slot = g_slot[e * TT + m];
                    const float gv = g_gval[e * TT + m];
                    float* yrow = g_Y + (size_t)slot * DIMC;
#pragma unroll
                    for (int nf = 0; nf < 8; nf++) {
                        const int col = n0 + wn * 64 + nf * 8 + tg * 2;
                        float2 v;
                        v.x = gv * (acc[mi][nf][i2 * 2 + 0] + be[col]);
                        v.y = gv * (acc[mi][nf][i2 * 2 + 1] + be[col + 1]);
                        *(float2*)(yrow + col) = v;
                    }
                } else {
#pragma unroll
                    for (int nf = 0; nf < 8; nf++) {
#pragma unroll
                        for (int j = 0; j < 2; j++) {
                            const int col = n0 + wn * 64 + nf * 8 + tg * 2 + j;
                            float v = acc[mi][nf][i2 * 2 + j] + be[col];
                            if constexpr (MODE == 0) {
                                g_A[(size_t)(e * TT + m) * (2 * DIMC) + DIMC + col] = tf32r(v);
                            } else {
                                g_H[(size_t)(e * TT + m) * MLPD + col] = tf32r(gelu_fast(v));
                            }
                        }
                    }
                }
            }
        }
    }
}

// ---------------- combine: out[tok] = Y[2*tok] + Y[2*tok+1] ----------------
__global__ void combine_kernel(float* __restrict__ outp) {
    const int idx = blockIdx.x * blockDim.x + threadIdx.x;
    if (idx >= TT * (DIMC / 4)) return;
    const int tk = idx >> 8, c4 = idx & 255;
    const float4 a = ((const float4*)(g_Y + (size_t)(2 * tk) * DIMC))[c4];
    const float4 b = ((const float4*)(g_Y + (size_t)(2 * tk + 1) * DIMC))[c4];
    float4 o;
    o.x = a.x + b.x; o.y = a.y + b.y; o.z = a.z + b.z; o.w = a.w + b.w;
    ((float4*)(outp + (size_t)tk * DIMC))[c4] = o;
}

// ---------------- moe_loss (deterministic fixed-order reduction) ----------------
__global__ void loss_kernel(float* __restrict__ outp, int out_size) {
    __shared__ float part[256 * EXP];
    const int tid = threadIdx.x;
    float l[EXP];
    for (int e = 0; e < EXP; e++) l[e] = 0.f;
    for (int tk = tid; tk < TT; tk += 256) {
        l[g_toke[2 * tk]] += g_tokg[2 * tk];
        l[g_toke[2 * tk + 1]] += g_tokg[2 * tk + 1];
    }
    for (int e = 0; e < EXP; e++) part[tid * EXP + e] = l[e];
    __syncthreads();
    for (int s = 128; s >= 1; s >>= 1) {
        if (tid < s)
            for (int e = 0; e < EXP; e++) part[tid * EXP + e] += part[(tid + s) * EXP + e];
        __syncthreads();
    }
    if (tid == 0) {
        float m = 0.f;
        for (int e = 0; e < EXP; e++) m += part[e];
        m *= (1.0f / EXP);
        float v = 0.f;
        for (int e = 0; e < EXP; e++) { float d = part[e] - m; v += d * d; }
        v /= (float)(EXP - 1);
        float bal = v / (m * m + 1e-10f);
        if (out_size > TT * DIMC) outp[TT * DIMC] = 2.f * bal;
    }
}

// ---------------- launcher ----------------
// Launch order: prep(1), route(2), gemm0(3), gemm1(4) <- ncu capture slot, gemm2(5), ...
extern "C" void kernel_launch(void* const* d_in, const int* in_sizes, int n_in,
                              void* d_out, int out_size) {
    const float* x      = (const float*)d_in[0];
    const float* prompt = (const float*)d_in[1];
    const float* t      = (const float*)d_in[2];
    const float* te_w1  = (const float*)d_in[3];
    const float* te_b1  = (const float*)d_in[4];
    const float* te_w2  = (const float*)d_in[5];
    const float* te_b2  = (const float*)d_in[6];
    const float* gate_w = (const float*)d_in[7];
    const float* ex_tw1 = (const float*)d_in[8];
    const float* ex_tb1 = (const float*)d_in[9];
    const float* ex_tw2 = (const float*)d_in[10];
    const float* ex_tb2 = (const float*)d_in[11];
    const float* ex_mw1 = (const float*)d_in[12];
    const float* ex_mb1 = (const float*)d_in[13];
    const float* ex_mw2 = (const float*)d_in[14];
    const float* ex_mb2 = (const float*)d_in[15];
    float* out = (float*)d_out;
    (void)in_sizes; (void)n_in;

    static int smem_set = 0;
    if (!smem_set) {
        cudaFuncSetAttribute(gemm_tf32_kernel<0>, cudaFuncAttributeMaxDynamicSharedMemorySize, GEMM_SMEM);
        cudaFuncSetAttribute(gemm_tf32_kernel<1>, cudaFuncAttributeMaxDynamicSharedMemorySize, GEMM_SMEM);
        cudaFuncSetAttribute(gemm_tf32_kernel<2>, cudaFuncAttributeMaxDynamicSharedMemorySize, GEMM_SMEM);
        smem_set = 1;
    }

    prep_kernel<<<DIMC + 1, 256>>>(te_w2, gate_w, te_b2);
    route_kernel<<<TT, 128>>>(x, prompt, t, te_w1, te_b1, gate_w, ex_tw1, ex_tb1);

    gemm_tf32_kernel<0><<<dim3(1024 / BN, TT / BM, EXP), 128, GEMM_SMEM>>>(ex_tw2, ex_tb2, out);
    gemm_tf32_kernel<1><<<dim3(4096 / BN, TT / BM, EXP), 128, GEMM_SMEM>>>(ex_mw1, ex_mb1, out);
    gemm_tf32_kernel<2><<<dim3(1024 / BN, TT / BM, EXP), 128, GEMM_SMEM>>>(ex_mw2, ex_mb2, out);

    combine_kernel<<<(TT * (DIMC / 4) + 255) / 256, 256>>>(out);
    loss_kernel<<<1, 256>>>(out, out_size);
}

// round 10
// speedup vs baseline: 1.3030x; 1.0263x over previous
#include <cuda_runtime.h>
#include <math.h>
#include <stdint.h>

// Problem constants
#define DIMC 1024
#define EXP  8
#define TT   4096            // tokens = B*N
#define MLPD 4096
#define TOTROW (EXP*TT)

// ---------------- scratch (static device allocations; no cudaMalloc) ----------------
__device__ float g_G[(size_t)TOTROW * DIMC];        // gelu(t*tw1+tb1) rows (tf32-rounded)
__device__ float g_A[(size_t)TOTROW * 2 * DIMC];    // [x | te] concat rows (tf32-rounded)
__device__ float g_H[(size_t)TOTROW * MLPD];        // hidden after gelu   (tf32-rounded)
__device__ float g_Y[(size_t)2 * TT * DIMC];        // per-slot expert outputs (gated)
__device__ int   g_cnt[EXP];
__device__ int   g_rowsmap[TOTROW];
__device__ int   g_slot[TOTROW];
__device__ float g_gval[TOTROW];
__device__ int   g_toke[2*TT];
__device__ float g_tokg[2*TT];
__device__ float g_M2[DIMC*EXP];
__device__ float g_b2w[EXP];

// Fast exact-erf gelu: Abramowitz-Stegun 7.1.26, |abs err| <= 1.5e-7
__device__ __forceinline__ float gelu_fast(float v) {
    float u = fabsf(v) * 0.70710678118654752f;
    float t = __fdividef(1.0f, fmaf(0.3275911f, u, 1.0f));
    float p = fmaf(t, 1.061405429f, -1.453152027f);
    p = fmaf(t, p, 1.421413741f);
    p = fmaf(t, p, -0.284496736f);
    p = fmaf(t, p, 0.254829592f);
    p = p * t;
    float er = 1.0f - p * __expf(-u * u);
    er = (v < 0.f) ? -er : er;
    return 0.5f * v * (1.0f + er);
}

__device__ __forceinline__ unsigned smem_u32(const void* p) {
    unsigned r;
    asm("{ .reg .u64 t; cvta.to.shared.u64 t, %1; cvt.u32.u64 %0, t; }" : "=r"(r) : "l"(p));
    return r;
}
__device__ __forceinline__ unsigned to_tf32(float f) {
    unsigned r; asm("cvt.rna.tf32.f32 %0, %1;" : "=r"(r) : "f"(f)); return r;
}
__device__ __forceinline__ float tf32r(float f) { return __uint_as_float(to_tf32(f)); }

// ---------------- prep: fold time-embed second matmul into gating + zero counters ----
__global__ void prep_kernel(const float* __restrict__ te_w2,
                            const float* __restrict__ gate_w,
                            const float* __restrict__ te_b2) {
    __shared__ float sred[256 * EXP];
    const int tid = threadIdx.x;
    if (blockIdx.x == 0 && tid < EXP) g_cnt[tid] = 0;
    float acc[EXP];
#pragma unroll
    for (int e = 0; e < EXP; e++) acc[e] = 0.f;
    const float* src = (blockIdx.x < DIMC) ? (te_w2 + (size_t)blockIdx.x * DIMC) : te_b2;
    for (int d = tid; d < DIMC; d += 256) {
        float wv = src[d];
        const float* gr = gate_w + (size_t)(2 * DIMC + d) * EXP;
#pragma unroll
        for (int e = 0; e < EXP; e++) acc[e] += wv * gr[e];
    }
#pragma unroll
    for (int e = 0; e < EXP; e++) sred[tid * EXP + e] = acc[e];
    __syncthreads();
    for (int s = 128; s >= 1; s >>= 1) {
        if (tid < s)
#pragma unroll
            for (int e = 0; e < EXP; e++) sred[tid * EXP + e] += sred[(tid + s) * EXP + e];
        __syncthreads();
    }
    if (tid < EXP) {
        if (blockIdx.x < DIMC) g_M2[blockIdx.x * EXP + tid] = sred[tid];
        else g_b2w[tid] = sred[tid];
    }
}

// ---------------- routing + gather fused: logits, top-2, softmax, scatter rows -------
__global__ void route_kernel(const float* __restrict__ x, const float* __restrict__ p,
                             const float* __restrict__ t,
                             const float* __restrict__ te_w1, const float* __restrict__ te_b1,
                             const float* __restrict__ gw,
                             const float* __restrict__ ex_tw1, const float* __restrict__ ex_tb1) {
    __shared__ float g[DIMC];
    __shared__ float part[128];
    __shared__ float logits[EXP];
    __shared__ int   s_e[2], s_p[2];
    const int tok = blockIdx.x;
    const int tid = threadIdx.x;
    const float tv = t[tok];
    for (int k = tid; k < DIMC; k += 128) g[k] = gelu_fast(tv * te_w1[k] + te_b1[k]);
    __syncthreads();

    const int e = tid & 7, seg = tid >> 3;
    const float* xr = x + (size_t)tok * DIMC;
    const float* pr = p + (size_t)tok * DIMC;
    float acc = 0.f;
    const int k0 = seg * 64;
    for (int k = k0; k < k0 + 64; k++) {
        acc += xr[k] * gw[(size_t)k * EXP + e];
        acc += pr[k] * gw[(size_t)(DIMC + k) * EXP + e];
        acc += g[k] * g_M2[k * EXP + e];
    }
    part[tid] = acc;
    __syncthreads();
    for (int s = 64; s >= 8; s >>= 1) {
        if (tid < s) part[tid] += part[tid + s];
        __syncthreads();
    }
    if (tid < 8) logits[tid] = part[tid] + g_b2w[tid];
    __syncthreads();

    if (tid == 0) {
        float b = -1e30f; int bi = 0;
        for (int i = 0; i < EXP; i++) { float v = logits[i]; if (v > b) { b = v; bi = i; } }
        float s2 = -1e30f; int si = 0;
        for (int i = 0; i < EXP; i++) { if (i == bi) continue; float v = logits[i]; if (v > s2) { s2 = v; si = i; } }
        float e1 = expf(s2 - b);
        float den = 1.f + e1;
        float gb = 1.f / den, gs = e1 / den;
        int p0 = atomicAdd(&g_cnt[bi], 1);
        g_rowsmap[bi * TT + p0] = tok; g_gval[bi * TT + p0] = gb; g_slot[bi * TT + p0] = 2 * tok;
        int p1 = atomicAdd(&g_cnt[si], 1);
        g_rowsmap[si * TT + p1] = tok; g_gval[si * TT + p1] = gs; g_slot[si * TT + p1] = 2 * tok + 1;
        g_toke[2 * tok] = bi;  g_tokg[2 * tok] = gb;
        g_toke[2 * tok + 1] = si; g_tokg[2 * tok + 1] = gs;
        s_e[0] = bi; s_p[0] = p0; s_e[1] = si; s_p[1] = p1;
    }
    __syncthreads();

    // fused gather: scatter tf32(x) into both expert A rows, compute G rows
    const int e0 = s_e[0], q0 = s_p[0], e1s = s_e[1], q1 = s_p[1];
    const float4* xr4 = (const float4*)xr;
    float4* a0 = (float4*)(g_A + (size_t)(e0 * TT + q0) * (2 * DIMC));
    float4* a1 = (float4*)(g_A + (size_t)(e1s * TT + q1) * (2 * DIMC));
    for (int k = tid; k < DIMC / 4; k += 128) {
        float4 v = xr4[k];
        v.x = tf32r(v.x); v.y = tf32r(v.y); v.z = tf32r(v.z); v.w = tf32r(v.w);
        a0[k] = v; a1[k] = v;
    }
#pragma unroll
    for (int j = 0; j < 2; j++) {
        const int ee = s_e[j], pp = s_p[j];
        const float* w1 = ex_tw1 + (size_t)ee * DIMC;
        const float* b1 = ex_tb1 + (size_t)ee * DIMC;
        float* Gr = g_G + (size_t)(ee * TT + pp) * DIMC;
        for (int k = tid; k < DIMC; k += 128) Gr[k] = tf32r(gelu_fast(tv * w1[k] + b1[k]));
    }
}

// ---------------- grouped tf32 GEMM: CTA 128x128, 4 warps 64x64, reg-double-buffered -
// MODE 0: te = G[M,1024] @ tw2 + tb2  -> g_A[:,1024:2048] (tf32-rounded)
// MODE 1: H  = gelu(A[M,2048] @ mw1 + mb1)  (tf32-rounded)
// MODE 2: Y  = H[M,4096] @ mw2 + mb2; g_Y[slot] = gate*Y (no atomics)
#define BM 128
#define BN 128
#define BK 32
#define STGS 3
#define ASTR 36
#define BSTR 136
#define A_STAGE (BM * ASTR)
#define B_STAGE (BK * BSTR)
#define GEMM_SMEM (STGS * (A_STAGE + B_STAGE) * 4)

template <int MODE>
__global__ __launch_bounds__(128, 2) void gemm_tf32_kernel(
    const float* __restrict__ B, const float* __restrict__ bias, float* __restrict__ outp) {
    constexpr int K = (MODE == 0) ? 1024 : (MODE == 1) ? 2048 : 4096;
    constexpr int N = (MODE == 1) ? 4096 : 1024;

    const int e = blockIdx.z;
    const int cnt = g_cnt[e];
    const int m0 = blockIdx.y * BM;
    if (m0 >= cnt) return;
    const int n0 = blockIdx.x * BN;

    const float* Abase = (MODE == 0) ? g_G : (MODE == 1) ? g_A : g_H;
    const float* Ae = Abase + ((size_t)e * TT + m0) * K;   // lda == K
    const float* Be = B + (size_t)e * K * N + n0;

    extern __shared__ float sm[];
    float* Asm = sm;
    float* Bsm = sm + STGS * A_STAGE;

    const int tid = threadIdx.x;
    const int lane = tid & 31, warp = tid >> 5;
    const int wm = warp & 1, wn = warp >> 1;           // 2x2 warps, each 64M x 64N
    const int gq = lane >> 2, tg = lane & 3;

    float acc[4][8][4];
#pragma unroll
    for (int a = 0; a < 4; a++)
#pragma unroll
        for (int b = 0; b < 8; b++)
#pragma unroll
            for (int c = 0; c < 4; c++) acc[a][b][c] = 0.f;

    // register fragment double-buffers
    unsigned ra[2][4][4];
    unsigned rbf[2][8][2];

    auto load_tile = [&](int kt, int st) {
        const int k0 = kt * BK;
        float* as = Asm + st * A_STAGE;
        float* bs = Bsm + st * B_STAGE;
#pragma unroll
        for (int i = 0; i < 8; i++) {                    // A: 128 rows x 32 floats
            int ch = tid + i * 128;
            int row = ch >> 3, c4 = (ch & 7) << 2;
            unsigned dst = smem_u32(as + row * ASTR + c4);
            const float* src = Ae + (size_t)row * K + k0 + c4;
            asm volatile("cp.async.cg.shared.global [%0],[%1],16;\n" ::"r"(dst), "l"(src));
        }
#pragma unroll
        for (int i = 0; i < 8; i++) {                    // B: 32 rows x 128 floats
            int ch = tid + i * 128;
            int kr = ch >> 5, c4 = (ch & 31) << 2;
            unsigned dst = smem_u32(bs + kr * BSTR + c4);
            const float* src = Be + (size_t)(k0 + kr) * N + c4;
            asm volatile("cp.async.cg.shared.global [%0],[%1],16;\n" ::"r"(dst), "l"(src));
        }
        asm volatile("cp.async.commit_group;\n");
    };

    auto load_frag = [&](const float* as, const float* bs, int ks, int buf) {
#pragma unroll
        for (int mi = 0; mi < 4; mi++) {
            int rbase = wm * 64 + mi * 16;
            ra[buf][mi][0] = __float_as_uint(as[(rbase + gq) * ASTR + ks * 8 + tg]);
            ra[buf][mi][1] = __float_as_uint(as[(rbase + gq + 8) * ASTR + ks * 8 + tg]);
            ra[buf][mi][2] = __float_as_uint(as[(rbase + gq) * ASTR + ks * 8 + tg + 4]);
            ra[buf][mi][3] = __float_as_uint(as[(rbase + gq + 8) * ASTR + ks * 8 + tg + 4]);
        }
#pragma unroll
        for (int nf = 0; nf < 8; nf++) {
            int nb = wn * 64 + nf * 8;
            rbf[buf][nf][0] = to_tf32(bs[(ks * 8 + tg) * BSTR + nb + gq]);
            rbf[buf][nf][1] = to_tf32(bs[(ks * 8 + tg + 4) * BSTR + nb + gq]);
        }
    };

    auto mma_slice = [&](int buf) {
#pragma unroll
        for (int nf = 0; nf < 8; nf++) {
#pragma unroll
            for (int mi = 0; mi < 4; mi++) {
                asm volatile(
                    "mma.sync.aligned.m16n8k8.row.col.f32.tf32.tf32.f32 "
                    "{%0,%1,%2,%3},{%4,%5,%6,%7},{%8,%9},{%0,%1,%2,%3};"
                    : "+f"(acc[mi][nf][0]), "+f"(acc[mi][nf][1]),
                      "+f"(acc[mi][nf][2]), "+f"(acc[mi][nf][3])
                    : "r"(ra[buf][mi][0]), "r"(ra[buf][mi][1]),
                      "r"(ra[buf][mi][2]), "r"(ra[buf][mi][3]),
                      "r"(rbf[buf][nf][0]), "r"(rbf[buf][nf][1]));
            }
        }
    };

    constexpr int KT = K / BK;
    load_tile(0, 0);
    load_tile(1, 1);

    int st = 0, ld = 2;                                  // stage counters mod 3
    for (int kt = 0; kt < KT; kt++) {
        if (kt + 2 < KT) { asm volatile("cp.async.wait_group 1;\n"); }
        else             { asm volatile("cp.async.wait_group 0;\n"); }
        __syncthreads();
        const float* as = Asm + st * A_STAGE;
        const float* bs = Bsm + st * B_STAGE;
        // prime fragment pipeline for this tile
        load_frag(as, bs, 0, 0);
        // issue next tile's cp.async AFTER the barrier (stage ld == (kt-1)%3,
        // last read before the barrier by every warp -> overwrite is safe)
        if (kt + 2 < KT) {
            load_tile(kt + 2, ld);
            if (++ld == STGS) ld = 0;
        }
#pragma unroll
        for (int ks = 0; ks < 4; ks++) {
            if (ks < 3) load_frag(as, bs, ks + 1, (ks + 1) & 1);  // prefetch next slice
            mma_slice(ks & 1);                                     // MMAs overlap the LDS
        }
        if (++st == STGS) st = 0;
    }

    // epilogue
    const float* be = bias + (size_t)e * N;
#pragma unroll
    for (int mi = 0; mi < 4; mi++) {
#pragma unroll
        for (int i2 = 0; i2 < 2; i2++) {
            const int lm = wm * 64 + mi * 16 + gq + i2 * 8;
            const int m = m0 + lm;
            if (m < cnt) {
                if constexpr (MODE == 2) {
                    const int slot = g_slot[e * TT + m];
                    const float gv = g_gval[e * TT + m];
                    float* yrow = g_Y + (size_t)slot * DIMC;
#pragma unroll
                    for (int nf = 0; nf < 8; nf++) {
                        const int col = n0 + wn * 64 + nf * 8 + tg * 2;
                        float2 v;
                        v.x = gv * (acc[mi][nf][i2 * 2 + 0] + be[col]);
                        v.y = gv * (acc[mi][nf][i2 * 2 + 1] + be[col + 1]);
                        *(float2*)(yrow + col) = v;
                    }
                } else {
#pragma unroll
                    for (int nf = 0; nf < 8; nf++) {
#pragma unroll
                        for (int j = 0; j < 2; j++) {
                            const int col = n0 + wn * 64 + nf * 8 + tg * 2 + j;
                            float v = acc[mi][nf][i2 * 2 + j] + be[col];
                            if constexpr (MODE == 0) {
                                g_A[(size_t)(e * TT + m) * (2 * DIMC) + DIMC + col] = tf32r(v);
                            } else {
                                g_H[(size_t)(e * TT + m) * MLPD + col] = tf32r(gelu_fast(v));
                            }
                        }
                    }
                }
            }
        }
    }
}

// ---------------- combine: out[tok] = Y[2*tok] + Y[2*tok+1] ----------------
__global__ void combine_kernel(float* __restrict__ outp) {
    const int idx = blockIdx.x * blockDim.x + threadIdx.x;
    if (idx >= TT * (DIMC / 4)) return;
    const int tk = idx >> 8, c4 = idx & 255;
    const float4 a = ((const float4*)(g_Y + (size_t)(2 * tk) * DIMC))[c4];
    const float4 b = ((const float4*)(g_Y + (size_t)(2 * tk + 1) * DIMC))[c4];
    float4 o;
    o.x = a.x + b.x; o.y = a.y + b.y; o.z = a.z + b.z; o.w = a.w + b.w;
    ((float4*)(outp + (size_t)tk * DIMC))[c4] = o;
}

// ---------------- moe_loss (deterministic fixed-order reduction) ----------------
__global__ void loss_kernel(float* __restrict__ outp, int out_size) {
    __shared__ float part[256 * EXP];
    const int tid = threadIdx.x;
    float l[EXP];
    for (int e = 0; e < EXP; e++) l[e] = 0.f;
    for (int tk = tid; tk < TT; tk += 256) {
        l[g_toke[2 * tk]] += g_tokg[2 * tk];
        l[g_toke[2 * tk + 1]] += g_tokg[2 * tk + 1];
    }
    for (int e = 0; e < EXP; e++) part[tid * EXP + e] = l[e];
    __syncthreads();
    for (int s = 128; s >= 1; s >>= 1) {
        if (tid < s)
            for (int e = 0; e < EXP; e++) part[tid * EXP + e] += part[(tid + s) * EXP + e];
        __syncthreads();
    }
    if (tid == 0) {
        float m = 0.f;
        for (int e = 0; e < EXP; e++) m += part[e];
        m *= (1.0f / EXP);
        float v = 0.f;
        for (int e = 0; e < EXP; e++) { float d = part[e] - m; v += d * d; }
        v /= (float)(EXP - 1);
        float bal = v / (m * m + 1e-10f);
        if (out_size > TT * DIMC) outp[TT * DIMC] = 2.f * bal;
    }
}

// ---------------- launcher ----------------
// Launch order: prep(1), route(2), gemm0(3), gemm1(4) <- ncu capture slot, gemm2(5), ...
extern "C" void kernel_launch(void* const* d_in, const int* in_sizes, int n_in,
                              void* d_out, int out_size) {
    const float* x      = (const float*)d_in[0];
    const float* prompt = (const float*)d_in[1];
    const float* t      = (const float*)d_in[2];
    const float* te_w1  = (const float*)d_in[3];
    const float* te_b1  = (const float*)d_in[4];
    const float* te_w2  = (const float*)d_in[5];
    const float* te_b2  = (const float*)d_in[6];
    const float* gate_w = (const float*)d_in[7];
    const float* ex_tw1 = (const float*)d_in[8];
    const float* ex_tb1 = (const float*)d_in[9];
    const float* ex_tw2 = (const float*)d_in[10];
    const float* ex_tb2 = (const float*)d_in[11];
    const float* ex_mw1 = (const float*)d_in[12];
    const float* ex_mb1 = (const float*)d_in[13];
    const float* ex_mw2 = (const float*)d_in[14];
    const float* ex_mb2 = (const float*)d_in[15];
    float* out = (float*)d_out;
    (void)in_sizes; (void)n_in;

    static int smem_set = 0;
    if (!smem_set) {
        cudaFuncSetAttribute(gemm_tf32_kernel<0>, cudaFuncAttributeMaxDynamicSharedMemorySize, GEMM_SMEM);
        cudaFuncSetAttribute(gemm_tf32_kernel<1>, cudaFuncAttributeMaxDynamicSharedMemorySize, GEMM_SMEM);
        cudaFuncSetAttribute(gemm_tf32_kernel<2>, cudaFuncAttributeMaxDynamicSharedMemorySize, GEMM_SMEM);
        smem_set = 1;
    }

    prep_kernel<<<DIMC + 1, 256>>>(te_w2, gate_w, te_b2);
    route_kernel<<<TT, 128>>>(x, prompt, t, te_w1, te_b1, gate_w, ex_tw1, ex_tb1);

    gemm_tf32_kernel<0><<<dim3(1024 / BN, TT / BM, EXP), 128, GEMM_SMEM>>>(ex_tw2, ex_tb2, out);
    gemm_tf32_kernel<1><<<dim3(4096 / BN, TT / BM, EXP), 128, GEMM_SMEM>>>(ex_mw1, ex_mb1, out);
    gemm_tf32_kernel<2><<<dim3(1024 / BN, TT / BM, EXP), 128, GEMM_SMEM>>>(ex_mw2, ex_mb2, out);

    combine_kernel<<<(TT * (DIMC / 4) + 255) / 256, 256>>>(out);
    loss_kernel<<<1, 256>>>(out, out_size);
}